// round 10
// baseline (speedup 1.0000x reference)
#include <cuda_runtime.h>

// NeighborlistVerletNsq: all-pairs PBC displacement + cutoff mask.
// Output layout (float32, element offsets, P = N(N-1)/2 unique pairs):
//   [0P..1P)  i   [1P..2P) j   [2P..3P) j   [3P..4P) i
//   [4P..5P)  d   [5P..6P) d
//   [6P..9P)  r (row-major [P,3])   [9P..12P) -r
//   [12P..13P) mask  [13P..14P) mask
//
// R5: analytic triu indices (no index reads) -> pure write stream.
// R8: 8 pairs/thread + 256-bit .cs stores (halves store l1tex events).
// R10: per-thread contiguous pj window: 8 consecutive j -> 24 contiguous
//      floats, loaded as 7 aligned LDG.128 (vs 24 scalar LDG.32). The
//      window misalignment (3*j0 mod 4) is warp-uniform -> 4-way switch
//      with compile-time offset, fully static register extraction.

__device__ __forceinline__ void st8(float* p, float a, float b, float c, float d,
                                    float e, float f, float g, float h) {
    asm volatile("st.global.cs.v8.f32 [%0], {%1,%2,%3,%4,%5,%6,%7,%8};"
        :: "l"(p), "f"(a), "f"(b), "f"(c), "f"(d),
           "f"(e), "f"(f), "f"(g), "f"(h) : "memory");
}

__device__ __forceinline__ float wrap_pbc(float x, float L, float h) {
    // floor-mod of (x+h) into [0,L), then -h. Valid because t=x+h is in (-L,2L).
    float t = x + h;
    if (t >= L) t -= L;
    if (t < 0.0f) t += L;
    return t - h;
}

// start offset of row i in the triu(k=1) enumeration: S(i) = i*(2N-1-i)/2
__device__ __forceinline__ int row_start(int i, int N) {
    return (i * (2 * N - 1 - i)) >> 1;
}

// exact row index i such that row_start(i) <= p < row_start(i+1)
__device__ __forceinline__ int row_of(int p, int N) {
    const float A = (float)(2 * N - 1);
    float disc = A * A - 8.0f * (float)p;
    int i = (int)((A - sqrtf(disc)) * 0.5f);       // off by at most 1
    i = min(max(i, 0), N - 2);
    if (p >= row_start(i + 1, N) && i < N - 2) ++i;
    else if (p < row_start(i, N)) --i;
    return i;
}

template<int OFF>
__device__ __forceinline__ void pbc8_win(const float (&w)[28],
    float ax, float ay, float az,
    float Lx, float Ly, float Lz, float hx, float hy, float hz, float CUTOFF,
    float (&rx)[8], float (&ry)[8], float (&rz)[8], float (&dd)[8], float (&mk)[8])
{
    #pragma unroll
    for (int k = 0; k < 8; k++) {
        float x = ax - w[OFF + 3 * k + 0];
        float y = ay - w[OFF + 3 * k + 1];
        float z = az - w[OFF + 3 * k + 2];
        x = wrap_pbc(x, Lx, hx);
        y = wrap_pbc(y, Ly, hy);
        z = wrap_pbc(z, Lz, hz);
        float d = sqrtf(x * x + y * y + z * z);
        bool m = (d <= CUTOFF);
        rx[k] = m ? x : 0.0f;
        ry[k] = m ? y : 0.0f;
        rz[k] = m ? z : 0.0f;
        dd[k] = m ? d : 0.0f;
        mk[k] = m ? 1.0f : 0.0f;
    }
}

__global__ void __launch_bounds__(256, 3)
nlist_kernel(const float* __restrict__ pos,
             const float* __restrict__ box,
             float*       __restrict__ out,
             int P, int N)
{
    const int t  = blockIdx.x * blockDim.x + threadIdx.x;
    const int p0 = t * 8;
    if (p0 >= P) return;

    const float Lx = __ldg(box + 0);
    const float Ly = __ldg(box + 4);
    const float Lz = __ldg(box + 8);
    const float hx = 0.5f * Lx, hy = 0.5f * Ly, hz = 0.5f * Lz;
    const float CUTOFF = 0.5f;
    const size_t Ps = (size_t)P;

    if (p0 + 7 < P) {
        // ---- recover (i, j) for the 8 consecutive pairs ----
        int i = row_of(p0, N);
        int j = i + 1 + (p0 - row_start(i, N));
        const int i0 = i, j0 = j;

        int is[8], js[8];
        float fi[8], fj[8];
        #pragma unroll
        for (int k = 0; k < 8; k++) {
            is[k] = i; js[k] = j;
            fi[k] = (float)i; fj[k] = (float)j;
            ++j;
            if (j >= N) { ++i; j = i + 1; }
        }

        // Index regions first: DRAM busy while position gathers are in flight.
        st8(out + 0 * Ps + p0, fi[0],fi[1],fi[2],fi[3],fi[4],fi[5],fi[6],fi[7]);
        st8(out + 1 * Ps + p0, fj[0],fj[1],fj[2],fj[3],fj[4],fj[5],fj[6],fj[7]);
        st8(out + 2 * Ps + p0, fj[0],fj[1],fj[2],fj[3],fj[4],fj[5],fj[6],fj[7]);
        st8(out + 3 * Ps + p0, fi[0],fi[1],fi[2],fi[3],fi[4],fi[5],fi[6],fi[7]);

        float rx[8], ry[8], rz[8], dd[8], mk[8];
        const bool fast = (is[0] == is[7]) && (j0 + 10 <= N);

        if (fast) {
            // ---- contiguous window gather: 7 aligned LDG.128 ----
            const int e0   = 3 * j0;
            const int base = e0 & ~3;
            const int off  = e0 - base;            // warp-uniform (0..3)
            float w[28];
            const float4* s4 = (const float4*)(pos + base);
            #pragma unroll
            for (int r = 0; r < 7; r++) {
                const float4 v = __ldg(s4 + r);
                w[4*r+0] = v.x; w[4*r+1] = v.y; w[4*r+2] = v.z; w[4*r+3] = v.w;
            }
            // pi broadcast (same row for all 8 pairs)
            const float* pi = pos + 3 * (size_t)i0;
            const float ax = __ldg(pi + 0), ay = __ldg(pi + 1), az = __ldg(pi + 2);

            switch (off) {
                case 0: pbc8_win<0>(w, ax,ay,az, Lx,Ly,Lz,hx,hy,hz,CUTOFF, rx,ry,rz,dd,mk); break;
                case 1: pbc8_win<1>(w, ax,ay,az, Lx,Ly,Lz,hx,hy,hz,CUTOFF, rx,ry,rz,dd,mk); break;
                case 2: pbc8_win<2>(w, ax,ay,az, Lx,Ly,Lz,hx,hy,hz,CUTOFF, rx,ry,rz,dd,mk); break;
                default:pbc8_win<3>(w, ax,ay,az, Lx,Ly,Lz,hx,hy,hz,CUTOFF, rx,ry,rz,dd,mk); break;
            }
        } else {
            // ---- scalar gather fallback (row crossing / end of array) ----
            #pragma unroll
            for (int k = 0; k < 8; k++) {
                const float* pi = pos + 3 * (size_t)is[k];
                const float* pj = pos + 3 * (size_t)js[k];
                float x = __ldg(pi + 0) - __ldg(pj + 0);
                float y = __ldg(pi + 1) - __ldg(pj + 1);
                float z = __ldg(pi + 2) - __ldg(pj + 2);
                x = wrap_pbc(x, Lx, hx);
                y = wrap_pbc(y, Ly, hy);
                z = wrap_pbc(z, Lz, hz);
                float d = sqrtf(x * x + y * y + z * z);
                bool m = (d <= CUTOFF);
                rx[k] = m ? x : 0.0f;
                ry[k] = m ? y : 0.0f;
                rz[k] = m ? z : 0.0f;
                dd[k] = m ? d : 0.0f;
                mk[k] = m ? 1.0f : 0.0f;
            }
        }

        st8(out + 4 * Ps + p0, dd[0],dd[1],dd[2],dd[3],dd[4],dd[5],dd[6],dd[7]);
        st8(out + 5 * Ps + p0, dd[0],dd[1],dd[2],dd[3],dd[4],dd[5],dd[6],dd[7]);

        float* rp = out + 6 * Ps + 3 * (size_t)p0;
        st8(rp +  0, rx[0],ry[0],rz[0], rx[1],ry[1],rz[1], rx[2],ry[2]);
        st8(rp +  8, rz[2], rx[3],ry[3],rz[3], rx[4],ry[4],rz[4], rx[5]);
        st8(rp + 16, ry[5],rz[5], rx[6],ry[6],rz[6], rx[7],ry[7],rz[7]);

        float* rn = out + 9 * Ps + 3 * (size_t)p0;
        st8(rn +  0, -rx[0],-ry[0],-rz[0], -rx[1],-ry[1],-rz[1], -rx[2],-ry[2]);
        st8(rn +  8, -rz[2], -rx[3],-ry[3],-rz[3], -rx[4],-ry[4],-rz[4], -rx[5]);
        st8(rn + 16, -ry[5],-rz[5], -rx[6],-ry[6],-rz[6], -rx[7],-ry[7],-rz[7]);

        st8(out + 12 * Ps + p0, mk[0],mk[1],mk[2],mk[3],mk[4],mk[5],mk[6],mk[7]);
        st8(out + 13 * Ps + p0, mk[0],mk[1],mk[2],mk[3],mk[4],mk[5],mk[6],mk[7]);
    } else {
        // ---- scalar tail ----
        for (int p = p0; p < P; p++) {
            int i = row_of(p, N);
            int j = i + 1 + (p - row_start(i, N));
            const float* pi = pos + 3 * (size_t)i;
            const float* pj = pos + 3 * (size_t)j;
            float x = __ldg(pi + 0) - __ldg(pj + 0);
            float y = __ldg(pi + 1) - __ldg(pj + 1);
            float z = __ldg(pi + 2) - __ldg(pj + 2);
            x = wrap_pbc(x, Lx, hx);
            y = wrap_pbc(y, Ly, hy);
            z = wrap_pbc(z, Lz, hz);
            float d = sqrtf(x * x + y * y + z * z);
            bool m = (d <= CUTOFF);
            float mx = m ? x : 0.0f, my = m ? y : 0.0f, mz = m ? z : 0.0f;
            float md = m ? d : 0.0f, mv = m ? 1.0f : 0.0f;

            out[ 0 * Ps + p] = (float)i;
            out[ 1 * Ps + p] = (float)j;
            out[ 2 * Ps + p] = (float)j;
            out[ 3 * Ps + p] = (float)i;
            out[ 4 * Ps + p] = md;
            out[ 5 * Ps + p] = md;
            out[ 6 * Ps + 3 * (size_t)p + 0] =  mx;
            out[ 6 * Ps + 3 * (size_t)p + 1] =  my;
            out[ 6 * Ps + 3 * (size_t)p + 2] =  mz;
            out[ 9 * Ps + 3 * (size_t)p + 0] = -mx;
            out[ 9 * Ps + 3 * (size_t)p + 1] = -my;
            out[ 9 * Ps + 3 * (size_t)p + 2] = -mz;
            out[12 * Ps + p] = mv;
            out[13 * Ps + p] = mv;
        }
    }
}

extern "C" void kernel_launch(void* const* d_in, const int* in_sizes, int n_in,
                              void* d_out, int out_size)
{
    const float* pos = (const float*)d_in[0];   // [N,3] float32
    const float* box = (const float*)d_in[1];   // [3,3] float32
    // d_in[2]/d_in[3] (i_pairs/j_pairs) reconstructed analytically — not read.
    float* out = (float*)d_out;

    const int P = in_sizes[2];
    const int N = in_sizes[0] / 3;
    const int nthreads = (P + 7) / 8;
    const int block = 256;
    const int grid = (nthreads + block - 1) / block;
    nlist_kernel<<<grid, block>>>(pos, box, out, P, N);
}

// round 11
// speedup vs baseline: 1.2642x; 1.2642x over previous
#include <cuda_runtime.h>

// NeighborlistVerletNsq: all-pairs PBC displacement + cutoff mask.
// Output layout (float32, element offsets, P = N(N-1)/2 unique pairs):
//   [0P..1P)  i   [1P..2P) j   [2P..3P) j   [3P..4P) i
//   [4P..5P)  d   [5P..6P) d
//   [6P..9P)  r (row-major [P,3])   [9P..12P) -r
//   [12P..13P) mask  [13P..14P) mask
//
// R5:  analytic triu indices (no index reads) -> pure write stream.
// R8:  8 pairs/thread + 256-bit .cs stores (halves store l1tex events).
// R11: fast path uses same-row identity (j0+8<=N => 8 consecutive j):
//      broadcast i, incremental j, walking pj pointer -> no index arrays,
//      ~48 live regs -> 5 blocks/SM for higher occupancy (fill DRAM idle).

__device__ __forceinline__ void st8(float* p, float a, float b, float c, float d,
                                    float e, float f, float g, float h) {
    asm volatile("st.global.cs.v8.f32 [%0], {%1,%2,%3,%4,%5,%6,%7,%8};"
        :: "l"(p), "f"(a), "f"(b), "f"(c), "f"(d),
           "f"(e), "f"(f), "f"(g), "f"(h) : "memory");
}

__device__ __forceinline__ float wrap_pbc(float x, float L, float h) {
    // floor-mod of (x+h) into [0,L), then -h. Valid because t=x+h is in (-L,2L).
    float t = x + h;
    if (t >= L) t -= L;
    if (t < 0.0f) t += L;
    return t - h;
}

// start offset of row i in the triu(k=1) enumeration: S(i) = i*(2N-1-i)/2
__device__ __forceinline__ int row_start(int i, int N) {
    return (i * (2 * N - 1 - i)) >> 1;
}

// exact row index i such that row_start(i) <= p < row_start(i+1)
__device__ __forceinline__ int row_of(int p, int N) {
    const float A = (float)(2 * N - 1);
    float disc = A * A - 8.0f * (float)p;
    int i = (int)((A - sqrtf(disc)) * 0.5f);       // off by at most 1
    i = min(max(i, 0), N - 2);
    if (p >= row_start(i + 1, N) && i < N - 2) ++i;
    else if (p < row_start(i, N)) --i;
    return i;
}

__global__ void __launch_bounds__(256, 5)
nlist_kernel(const float* __restrict__ pos,
             const float* __restrict__ box,
             float*       __restrict__ out,
             int P, int N)
{
    const int t  = blockIdx.x * blockDim.x + threadIdx.x;
    const int p0 = t * 8;
    if (p0 >= P) return;

    const float Lx = __ldg(box + 0);
    const float Ly = __ldg(box + 4);
    const float Lz = __ldg(box + 8);
    const float hx = 0.5f * Lx, hy = 0.5f * Ly, hz = 0.5f * Lz;
    const float CUTOFF = 0.5f;
    const size_t Ps = (size_t)P;

    // recover (i0, j0) for the first pair
    const int i0 = row_of(p0, N);
    const int j0 = i0 + 1 + (p0 - row_start(i0, N));

    // 8 pairs stay in one triu row  <=>  j0+8 <= N  (then j's are consecutive)
    if (p0 + 7 < P && j0 + 8 <= N) {
        // ---- index regions first (no arrays: broadcast i, incremental j) ----
        const float fi0 = (float)i0;
        const float fj0 = (float)j0;
        st8(out + 0 * Ps + p0, fi0,fi0,fi0,fi0,fi0,fi0,fi0,fi0);
        st8(out + 1 * Ps + p0, fj0,fj0+1.f,fj0+2.f,fj0+3.f,fj0+4.f,fj0+5.f,fj0+6.f,fj0+7.f);
        st8(out + 2 * Ps + p0, fj0,fj0+1.f,fj0+2.f,fj0+3.f,fj0+4.f,fj0+5.f,fj0+6.f,fj0+7.f);
        st8(out + 3 * Ps + p0, fi0,fi0,fi0,fi0,fi0,fi0,fi0,fi0);

        // pi broadcast
        const float* pi = pos + 3 * (size_t)i0;
        const float ax = __ldg(pi + 0), ay = __ldg(pi + 1), az = __ldg(pi + 2);

        // pj: walking pointer over 24 contiguous floats
        const float* pj = pos + 3 * (size_t)j0;

        float rx[8], ry[8], rz[8], dd[8], mk[8];
        #pragma unroll
        for (int k = 0; k < 8; k++) {
            float x = ax - __ldg(pj + 3 * k + 0);
            float y = ay - __ldg(pj + 3 * k + 1);
            float z = az - __ldg(pj + 3 * k + 2);
            x = wrap_pbc(x, Lx, hx);
            y = wrap_pbc(y, Ly, hy);
            z = wrap_pbc(z, Lz, hz);
            float d = sqrtf(x * x + y * y + z * z);
            bool m = (d <= CUTOFF);
            rx[k] = m ? x : 0.0f;
            ry[k] = m ? y : 0.0f;
            rz[k] = m ? z : 0.0f;
            dd[k] = m ? d : 0.0f;
            mk[k] = m ? 1.0f : 0.0f;
        }

        // r regions first (frees rx/ry/rz), then d, then mask
        float* rp = out + 6 * Ps + 3 * (size_t)p0;
        st8(rp +  0, rx[0],ry[0],rz[0], rx[1],ry[1],rz[1], rx[2],ry[2]);
        st8(rp +  8, rz[2], rx[3],ry[3],rz[3], rx[4],ry[4],rz[4], rx[5]);
        st8(rp + 16, ry[5],rz[5], rx[6],ry[6],rz[6], rx[7],ry[7],rz[7]);

        float* rn = out + 9 * Ps + 3 * (size_t)p0;
        st8(rn +  0, -rx[0],-ry[0],-rz[0], -rx[1],-ry[1],-rz[1], -rx[2],-ry[2]);
        st8(rn +  8, -rz[2], -rx[3],-ry[3],-rz[3], -rx[4],-ry[4],-rz[4], -rx[5]);
        st8(rn + 16, -ry[5],-rz[5], -rx[6],-ry[6],-rz[6], -rx[7],-ry[7],-rz[7]);

        st8(out + 4 * Ps + p0, dd[0],dd[1],dd[2],dd[3],dd[4],dd[5],dd[6],dd[7]);
        st8(out + 5 * Ps + p0, dd[0],dd[1],dd[2],dd[3],dd[4],dd[5],dd[6],dd[7]);

        st8(out + 12 * Ps + p0, mk[0],mk[1],mk[2],mk[3],mk[4],mk[5],mk[6],mk[7]);
        st8(out + 13 * Ps + p0, mk[0],mk[1],mk[2],mk[3],mk[4],mk[5],mk[6],mk[7]);
    } else {
        // ---- scalar path: row crossing or tail ----
        int i = i0, j = j0;
        const int pend = min(p0 + 8, P);
        for (int p = p0; p < pend; p++) {
            const float* pi = pos + 3 * (size_t)i;
            const float* pj = pos + 3 * (size_t)j;
            float x = __ldg(pi + 0) - __ldg(pj + 0);
            float y = __ldg(pi + 1) - __ldg(pj + 1);
            float z = __ldg(pi + 2) - __ldg(pj + 2);
            x = wrap_pbc(x, Lx, hx);
            y = wrap_pbc(y, Ly, hy);
            z = wrap_pbc(z, Lz, hz);
            float d = sqrtf(x * x + y * y + z * z);
            bool m = (d <= CUTOFF);
            float mx = m ? x : 0.0f, my = m ? y : 0.0f, mz = m ? z : 0.0f;
            float md = m ? d : 0.0f, mv = m ? 1.0f : 0.0f;

            out[ 0 * Ps + p] = (float)i;
            out[ 1 * Ps + p] = (float)j;
            out[ 2 * Ps + p] = (float)j;
            out[ 3 * Ps + p] = (float)i;
            out[ 4 * Ps + p] = md;
            out[ 5 * Ps + p] = md;
            out[ 6 * Ps + 3 * (size_t)p + 0] =  mx;
            out[ 6 * Ps + 3 * (size_t)p + 1] =  my;
            out[ 6 * Ps + 3 * (size_t)p + 2] =  mz;
            out[ 9 * Ps + 3 * (size_t)p + 0] = -mx;
            out[ 9 * Ps + 3 * (size_t)p + 1] = -my;
            out[ 9 * Ps + 3 * (size_t)p + 2] = -mz;
            out[12 * Ps + p] = mv;
            out[13 * Ps + p] = mv;

            ++j;
            if (j >= N) { ++i; j = i + 1; }
        }
    }
}

extern "C" void kernel_launch(void* const* d_in, const int* in_sizes, int n_in,
                              void* d_out, int out_size)
{
    const float* pos = (const float*)d_in[0];   // [N,3] float32
    const float* box = (const float*)d_in[1];   // [3,3] float32
    // d_in[2]/d_in[3] (i_pairs/j_pairs) reconstructed analytically — not read.
    float* out = (float*)d_out;

    const int P = in_sizes[2];
    const int N = in_sizes[0] / 3;
    const int nthreads = (P + 7) / 8;
    const int block = 256;
    const int grid = (nthreads + block - 1) / block;
    nlist_kernel<<<grid, block>>>(pos, box, out, P, N);
}

// round 12
// speedup vs baseline: 1.4645x; 1.1584x over previous
#include <cuda_runtime.h>

// NeighborlistVerletNsq: all-pairs PBC displacement + cutoff mask.
// Output layout (float32, element offsets, P = N(N-1)/2 unique pairs):
//   [0P..1P)  i   [1P..2P) j   [2P..3P) j   [3P..4P) i
//   [4P..5P)  d   [5P..6P) d
//   [6P..9P)  r (row-major [P,3])   [9P..12P) -r
//   [12P..13P) mask  [13P..14P) mask
//
// R5:  analytic triu indices (no index reads) -> pure write stream.
// R8:  8 pairs/thread + 256-bit .cs stores (halves store l1tex events).
// R12: st8 without "memory" clobber -> ptxas may hoist the 24 gather LDGs
//      above/into the index-store block, overlapping load latency with
//      store issue. (Safe: store targets are never read, pos never written.)

__device__ __forceinline__ void st8(float* p, float a, float b, float c, float d,
                                    float e, float f, float g, float h) {
    asm volatile("st.global.cs.v8.f32 [%0], {%1,%2,%3,%4,%5,%6,%7,%8};"
        :: "l"(p), "f"(a), "f"(b), "f"(c), "f"(d),
           "f"(e), "f"(f), "f"(g), "f"(h));
}

__device__ __forceinline__ float wrap_pbc(float x, float L, float h) {
    // floor-mod of (x+h) into [0,L), then -h. Valid because t=x+h is in (-L,2L).
    float t = x + h;
    if (t >= L) t -= L;
    if (t < 0.0f) t += L;
    return t - h;
}

// start offset of row i in the triu(k=1) enumeration: S(i) = i*(2N-1-i)/2
__device__ __forceinline__ int row_start(int i, int N) {
    return (i * (2 * N - 1 - i)) >> 1;
}

// exact row index i such that row_start(i) <= p < row_start(i+1)
__device__ __forceinline__ int row_of(int p, int N) {
    const float A = (float)(2 * N - 1);
    float disc = A * A - 8.0f * (float)p;
    int i = (int)((A - sqrtf(disc)) * 0.5f);       // off by at most 1
    i = min(max(i, 0), N - 2);
    if (p >= row_start(i + 1, N) && i < N - 2) ++i;
    else if (p < row_start(i, N)) --i;
    return i;
}

__global__ void __launch_bounds__(256, 3)
nlist_kernel(const float* __restrict__ pos,
             const float* __restrict__ box,
             float*       __restrict__ out,
             int P, int N)
{
    const int t  = blockIdx.x * blockDim.x + threadIdx.x;
    const int p0 = t * 8;
    if (p0 >= P) return;

    const float Lx = __ldg(box + 0);
    const float Ly = __ldg(box + 4);
    const float Lz = __ldg(box + 8);
    const float hx = 0.5f * Lx, hy = 0.5f * Ly, hz = 0.5f * Lz;
    const float CUTOFF = 0.5f;
    const size_t Ps = (size_t)P;

    if (p0 + 7 < P) {
        // ---- recover (i, j) for the 8 consecutive pairs ----
        int i = row_of(p0, N);
        int j = i + 1 + (p0 - row_start(i, N));

        int is[8], js[8];
        float fi[8], fj[8];
        #pragma unroll
        for (int k = 0; k < 8; k++) {
            is[k] = i; js[k] = j;
            fi[k] = (float)i; fj[k] = (float)j;
            ++j;
            if (j >= N) { ++i; j = i + 1; }
        }

        // Index regions early: DRAM busy while position gathers are in flight.
        st8(out + 0 * Ps + p0, fi[0],fi[1],fi[2],fi[3],fi[4],fi[5],fi[6],fi[7]);
        st8(out + 1 * Ps + p0, fj[0],fj[1],fj[2],fj[3],fj[4],fj[5],fj[6],fj[7]);
        st8(out + 2 * Ps + p0, fj[0],fj[1],fj[2],fj[3],fj[4],fj[5],fj[6],fj[7]);
        st8(out + 3 * Ps + p0, fi[0],fi[1],fi[2],fi[3],fi[4],fi[5],fi[6],fi[7]);

        // pi gather; dedupe when all 8 pairs share row i (the common case)
        float ax[8], ay[8], az[8];
        if (is[0] == is[7]) {
            const float* pi = pos + 3 * (size_t)is[0];
            float x = __ldg(pi + 0), y = __ldg(pi + 1), z = __ldg(pi + 2);
            #pragma unroll
            for (int k = 0; k < 8; k++) { ax[k] = x; ay[k] = y; az[k] = z; }
        } else {
            #pragma unroll
            for (int k = 0; k < 8; k++) {
                const float* pi = pos + 3 * (size_t)is[k];
                ax[k] = __ldg(pi + 0); ay[k] = __ldg(pi + 1); az[k] = __ldg(pi + 2);
            }
        }

        float rx[8], ry[8], rz[8], dd[8], mk[8];
        #pragma unroll
        for (int k = 0; k < 8; k++) {
            const float* pj = pos + 3 * (size_t)js[k];
            float x = ax[k] - __ldg(pj + 0);
            float y = ay[k] - __ldg(pj + 1);
            float z = az[k] - __ldg(pj + 2);
            x = wrap_pbc(x, Lx, hx);
            y = wrap_pbc(y, Ly, hy);
            z = wrap_pbc(z, Lz, hz);
            float d = sqrtf(x * x + y * y + z * z);
            bool m = (d <= CUTOFF);
            rx[k] = m ? x : 0.0f;
            ry[k] = m ? y : 0.0f;
            rz[k] = m ? z : 0.0f;
            dd[k] = m ? d : 0.0f;
            mk[k] = m ? 1.0f : 0.0f;
        }

        st8(out + 4 * Ps + p0, dd[0],dd[1],dd[2],dd[3],dd[4],dd[5],dd[6],dd[7]);
        st8(out + 5 * Ps + p0, dd[0],dd[1],dd[2],dd[3],dd[4],dd[5],dd[6],dd[7]);

        float* rp = out + 6 * Ps + 3 * (size_t)p0;
        st8(rp +  0, rx[0],ry[0],rz[0], rx[1],ry[1],rz[1], rx[2],ry[2]);
        st8(rp +  8, rz[2], rx[3],ry[3],rz[3], rx[4],ry[4],rz[4], rx[5]);
        st8(rp + 16, ry[5],rz[5], rx[6],ry[6],rz[6], rx[7],ry[7],rz[7]);

        float* rn = out + 9 * Ps + 3 * (size_t)p0;
        st8(rn +  0, -rx[0],-ry[0],-rz[0], -rx[1],-ry[1],-rz[1], -rx[2],-ry[2]);
        st8(rn +  8, -rz[2], -rx[3],-ry[3],-rz[3], -rx[4],-ry[4],-rz[4], -rx[5]);
        st8(rn + 16, -ry[5],-rz[5], -rx[6],-ry[6],-rz[6], -rx[7],-ry[7],-rz[7]);

        st8(out + 12 * Ps + p0, mk[0],mk[1],mk[2],mk[3],mk[4],mk[5],mk[6],mk[7]);
        st8(out + 13 * Ps + p0, mk[0],mk[1],mk[2],mk[3],mk[4],mk[5],mk[6],mk[7]);
    } else {
        // ---- scalar tail ----
        for (int p = p0; p < P; p++) {
            int i = row_of(p, N);
            int j = i + 1 + (p - row_start(i, N));
            const float* pi = pos + 3 * (size_t)i;
            const float* pj = pos + 3 * (size_t)j;
            float x = __ldg(pi + 0) - __ldg(pj + 0);
            float y = __ldg(pi + 1) - __ldg(pj + 1);
            float z = __ldg(pi + 2) - __ldg(pj + 2);
            x = wrap_pbc(x, Lx, hx);
            y = wrap_pbc(y, Ly, hy);
            z = wrap_pbc(z, Lz, hz);
            float d = sqrtf(x * x + y * y + z * z);
            bool m = (d <= CUTOFF);
            float mx = m ? x : 0.0f, my = m ? y : 0.0f, mz = m ? z : 0.0f;
            float md = m ? d : 0.0f, mv = m ? 1.0f : 0.0f;

            out[ 0 * Ps + p] = (float)i;
            out[ 1 * Ps + p] = (float)j;
            out[ 2 * Ps + p] = (float)j;
            out[ 3 * Ps + p] = (float)i;
            out[ 4 * Ps + p] = md;
            out[ 5 * Ps + p] = md;
            out[ 6 * Ps + 3 * (size_t)p + 0] =  mx;
            out[ 6 * Ps + 3 * (size_t)p + 1] =  my;
            out[ 6 * Ps + 3 * (size_t)p + 2] =  mz;
            out[ 9 * Ps + 3 * (size_t)p + 0] = -mx;
            out[ 9 * Ps + 3 * (size_t)p + 1] = -my;
            out[ 9 * Ps + 3 * (size_t)p + 2] = -mz;
            out[12 * Ps + p] = mv;
            out[13 * Ps + p] = mv;
        }
    }
}

extern "C" void kernel_launch(void* const* d_in, const int* in_sizes, int n_in,
                              void* d_out, int out_size)
{
    const float* pos = (const float*)d_in[0];   // [N,3] float32
    const float* box = (const float*)d_in[1];   // [3,3] float32
    // d_in[2]/d_in[3] (i_pairs/j_pairs) reconstructed analytically — not read.
    float* out = (float*)d_out;

    const int P = in_sizes[2];
    const int N = in_sizes[0] / 3;
    const int nthreads = (P + 7) / 8;
    const int block = 256;
    const int grid = (nthreads + block - 1) / block;
    nlist_kernel<<<grid, block>>>(pos, box, out, P, N);
}

// round 13
// speedup vs baseline: 1.4758x; 1.0078x over previous
#include <cuda_runtime.h>
#include <cstdint>

// NeighborlistVerletNsq: all-pairs PBC displacement + cutoff mask.
// Output layout (float32, element offsets, P = N(N-1)/2 unique pairs):
//   [0P..1P)  i   [1P..2P) j   [2P..3P) j   [3P..4P) i
//   [4P..5P)  d   [5P..6P) d
//   [6P..9P)  r (row-major [P,3])   [9P..12P) -r
//   [12P..13P) mask  [13P..14P) mask
//
// R5:  analytic triu indices (no index reads) -> pure write stream.
// R8:  8 pairs/thread + 256-bit .cs stores (halves store l1tex events).
// R13: L2 residency partition: d/d/mask regions (100.5 MB < 126 MB L2)
//      stored with L2::evict_last policy -> across graph replays those
//      dirty lines are overwritten IN L2 and never cost DRAM writeback.
//      Everything else stays .cs (evict-first) so the streaming majority
//      doesn't disturb the resident set.

__device__ __forceinline__ void st8(float* p, float a, float b, float c, float d,
                                    float e, float f, float g, float h) {
    asm volatile("st.global.cs.v8.f32 [%0], {%1,%2,%3,%4,%5,%6,%7,%8};"
        :: "l"(p), "f"(a), "f"(b), "f"(c), "f"(d),
           "f"(e), "f"(f), "f"(g), "f"(h));
}

// store with L2 evict_last cache-policy (resident slice)
__device__ __forceinline__ void st8_keep(float* p, uint64_t pol,
                                    float a, float b, float c, float d,
                                    float e, float f, float g, float h) {
    asm volatile("st.global.L2::cache_hint.v8.f32 [%0], {%2,%3,%4,%5,%6,%7,%8,%9}, %1;"
        :: "l"(p), "l"(pol), "f"(a), "f"(b), "f"(c), "f"(d),
           "f"(e), "f"(f), "f"(g), "f"(h));
}

__device__ __forceinline__ float wrap_pbc(float x, float L, float h) {
    // floor-mod of (x+h) into [0,L), then -h. Valid because t=x+h is in (-L,2L).
    float t = x + h;
    if (t >= L) t -= L;
    if (t < 0.0f) t += L;
    return t - h;
}

// start offset of row i in the triu(k=1) enumeration: S(i) = i*(2N-1-i)/2
__device__ __forceinline__ int row_start(int i, int N) {
    return (i * (2 * N - 1 - i)) >> 1;
}

// exact row index i such that row_start(i) <= p < row_start(i+1)
__device__ __forceinline__ int row_of(int p, int N) {
    const float A = (float)(2 * N - 1);
    float disc = A * A - 8.0f * (float)p;
    int i = (int)((A - sqrtf(disc)) * 0.5f);       // off by at most 1
    i = min(max(i, 0), N - 2);
    if (p >= row_start(i + 1, N) && i < N - 2) ++i;
    else if (p < row_start(i, N)) --i;
    return i;
}

__global__ void __launch_bounds__(256, 3)
nlist_kernel(const float* __restrict__ pos,
             const float* __restrict__ box,
             float*       __restrict__ out,
             int P, int N)
{
    const int t  = blockIdx.x * blockDim.x + threadIdx.x;
    const int p0 = t * 8;
    if (p0 >= P) return;

    // L2 evict_last policy for the resident output slice
    uint64_t pol;
    asm("createpolicy.fractional.L2::evict_last.b64 %0, 1.0;" : "=l"(pol));

    const float Lx = __ldg(box + 0);
    const float Ly = __ldg(box + 4);
    const float Lz = __ldg(box + 8);
    const float hx = 0.5f * Lx, hy = 0.5f * Ly, hz = 0.5f * Lz;
    const float CUTOFF = 0.5f;
    const size_t Ps = (size_t)P;

    if (p0 + 7 < P) {
        // ---- recover (i, j) for the 8 consecutive pairs ----
        int i = row_of(p0, N);
        int j = i + 1 + (p0 - row_start(i, N));

        int is[8], js[8];
        float fi[8], fj[8];
        #pragma unroll
        for (int k = 0; k < 8; k++) {
            is[k] = i; js[k] = j;
            fi[k] = (float)i; fj[k] = (float)j;
            ++j;
            if (j >= N) { ++i; j = i + 1; }
        }

        // Index regions early: DRAM busy while position gathers are in flight.
        st8(out + 0 * Ps + p0, fi[0],fi[1],fi[2],fi[3],fi[4],fi[5],fi[6],fi[7]);
        st8(out + 1 * Ps + p0, fj[0],fj[1],fj[2],fj[3],fj[4],fj[5],fj[6],fj[7]);
        st8(out + 2 * Ps + p0, fj[0],fj[1],fj[2],fj[3],fj[4],fj[5],fj[6],fj[7]);
        st8(out + 3 * Ps + p0, fi[0],fi[1],fi[2],fi[3],fi[4],fi[5],fi[6],fi[7]);

        // pi gather; dedupe when all 8 pairs share row i (the common case)
        float ax[8], ay[8], az[8];
        if (is[0] == is[7]) {
            const float* pi = pos + 3 * (size_t)is[0];
            float x = __ldg(pi + 0), y = __ldg(pi + 1), z = __ldg(pi + 2);
            #pragma unroll
            for (int k = 0; k < 8; k++) { ax[k] = x; ay[k] = y; az[k] = z; }
        } else {
            #pragma unroll
            for (int k = 0; k < 8; k++) {
                const float* pi = pos + 3 * (size_t)is[k];
                ax[k] = __ldg(pi + 0); ay[k] = __ldg(pi + 1); az[k] = __ldg(pi + 2);
            }
        }

        float rx[8], ry[8], rz[8], dd[8], mk[8];
        #pragma unroll
        for (int k = 0; k < 8; k++) {
            const float* pj = pos + 3 * (size_t)js[k];
            float x = ax[k] - __ldg(pj + 0);
            float y = ay[k] - __ldg(pj + 1);
            float z = az[k] - __ldg(pj + 2);
            x = wrap_pbc(x, Lx, hx);
            y = wrap_pbc(y, Ly, hy);
            z = wrap_pbc(z, Lz, hz);
            float d = sqrtf(x * x + y * y + z * z);
            bool m = (d <= CUTOFF);
            rx[k] = m ? x : 0.0f;
            ry[k] = m ? y : 0.0f;
            rz[k] = m ? z : 0.0f;
            dd[k] = m ? d : 0.0f;
            mk[k] = m ? 1.0f : 0.0f;
        }

        // Resident slice: d, d-dup, mask (100.5 MB total) -> evict_last
        st8_keep(out + 4 * Ps + p0, pol, dd[0],dd[1],dd[2],dd[3],dd[4],dd[5],dd[6],dd[7]);
        st8_keep(out + 5 * Ps + p0, pol, dd[0],dd[1],dd[2],dd[3],dd[4],dd[5],dd[6],dd[7]);

        float* rp = out + 6 * Ps + 3 * (size_t)p0;
        st8(rp +  0, rx[0],ry[0],rz[0], rx[1],ry[1],rz[1], rx[2],ry[2]);
        st8(rp +  8, rz[2], rx[3],ry[3],rz[3], rx[4],ry[4],rz[4], rx[5]);
        st8(rp + 16, ry[5],rz[5], rx[6],ry[6],rz[6], rx[7],ry[7],rz[7]);

        float* rn = out + 9 * Ps + 3 * (size_t)p0;
        st8(rn +  0, -rx[0],-ry[0],-rz[0], -rx[1],-ry[1],-rz[1], -rx[2],-ry[2]);
        st8(rn +  8, -rz[2], -rx[3],-ry[3],-rz[3], -rx[4],-ry[4],-rz[4], -rx[5]);
        st8(rn + 16, -ry[5],-rz[5], -rx[6],-ry[6],-rz[6], -rx[7],-ry[7],-rz[7]);

        st8_keep(out + 12 * Ps + p0, pol, mk[0],mk[1],mk[2],mk[3],mk[4],mk[5],mk[6],mk[7]);
        st8(out + 13 * Ps + p0, mk[0],mk[1],mk[2],mk[3],mk[4],mk[5],mk[6],mk[7]);
    } else {
        // ---- scalar tail ----
        for (int p = p0; p < P; p++) {
            int i = row_of(p, N);
            int j = i + 1 + (p - row_start(i, N));
            const float* pi = pos + 3 * (size_t)i;
            const float* pj = pos + 3 * (size_t)j;
            float x = __ldg(pi + 0) - __ldg(pj + 0);
            float y = __ldg(pi + 1) - __ldg(pj + 1);
            float z = __ldg(pi + 2) - __ldg(pj + 2);
            x = wrap_pbc(x, Lx, hx);
            y = wrap_pbc(y, Ly, hy);
            z = wrap_pbc(z, Lz, hz);
            float d = sqrtf(x * x + y * y + z * z);
            bool m = (d <= CUTOFF);
            float mx = m ? x : 0.0f, my = m ? y : 0.0f, mz = m ? z : 0.0f;
            float md = m ? d : 0.0f, mv = m ? 1.0f : 0.0f;

            out[ 0 * Ps + p] = (float)i;
            out[ 1 * Ps + p] = (float)j;
            out[ 2 * Ps + p] = (float)j;
            out[ 3 * Ps + p] = (float)i;
            out[ 4 * Ps + p] = md;
            out[ 5 * Ps + p] = md;
            out[ 6 * Ps + 3 * (size_t)p + 0] =  mx;
            out[ 6 * Ps + 3 * (size_t)p + 1] =  my;
            out[ 6 * Ps + 3 * (size_t)p + 2] =  mz;
            out[ 9 * Ps + 3 * (size_t)p + 0] = -mx;
            out[ 9 * Ps + 3 * (size_t)p + 1] = -my;
            out[ 9 * Ps + 3 * (size_t)p + 2] = -mz;
            out[12 * Ps + p] = mv;
            out[13 * Ps + p] = mv;
        }
    }
}

extern "C" void kernel_launch(void* const* d_in, const int* in_sizes, int n_in,
                              void* d_out, int out_size)
{
    const float* pos = (const float*)d_in[0];   // [N,3] float32
    const float* box = (const float*)d_in[1];   // [3,3] float32
    // d_in[2]/d_in[3] (i_pairs/j_pairs) reconstructed analytically — not read.
    float* out = (float*)d_out;

    const int P = in_sizes[2];
    const int N = in_sizes[0] / 3;
    const int nthreads = (P + 7) / 8;
    const int block = 256;
    const int grid = (nthreads + block - 1) / block;
    nlist_kernel<<<grid, block>>>(pos, box, out, P, N);
}

// round 14
// speedup vs baseline: 1.4765x; 1.0005x over previous
#include <cuda_runtime.h>

// NeighborlistVerletNsq: all-pairs PBC displacement + cutoff mask.
// Output layout (float32, element offsets, P = N(N-1)/2 unique pairs):
//   [0P..1P)  i   [1P..2P) j   [2P..3P) j   [3P..4P) i
//   [4P..5P)  d   [5P..6P) d
//   [6P..9P)  r (row-major [P,3])   [9P..12P) -r
//   [12P..13P) mask  [13P..14P) mask
//
// Final form:
//  - analytic triu indices (no index reads) -> pure write stream (R5)
//  - 8 pairs/thread + 256-bit .cs stores (halves store l1tex events) (R8)
//  - no "memory" clobber on stores -> free LDG scheduling (R12)
//  - launch_bounds(256,4): 4 blocks/SM at 56 regs -> +33% warps to fill
//    DRAM idle gaps (R14)

__device__ __forceinline__ void st8(float* p, float a, float b, float c, float d,
                                    float e, float f, float g, float h) {
    asm volatile("st.global.cs.v8.f32 [%0], {%1,%2,%3,%4,%5,%6,%7,%8};"
        :: "l"(p), "f"(a), "f"(b), "f"(c), "f"(d),
           "f"(e), "f"(f), "f"(g), "f"(h));
}

__device__ __forceinline__ float wrap_pbc(float x, float L, float h) {
    // floor-mod of (x+h) into [0,L), then -h. Valid because t=x+h is in (-L,2L).
    float t = x + h;
    if (t >= L) t -= L;
    if (t < 0.0f) t += L;
    return t - h;
}

// start offset of row i in the triu(k=1) enumeration: S(i) = i*(2N-1-i)/2
__device__ __forceinline__ int row_start(int i, int N) {
    return (i * (2 * N - 1 - i)) >> 1;
}

// exact row index i such that row_start(i) <= p < row_start(i+1)
__device__ __forceinline__ int row_of(int p, int N) {
    const float A = (float)(2 * N - 1);
    float disc = A * A - 8.0f * (float)p;
    int i = (int)((A - sqrtf(disc)) * 0.5f);       // off by at most 1
    i = min(max(i, 0), N - 2);
    if (p >= row_start(i + 1, N) && i < N - 2) ++i;
    else if (p < row_start(i, N)) --i;
    return i;
}

__global__ void __launch_bounds__(256, 4)
nlist_kernel(const float* __restrict__ pos,
             const float* __restrict__ box,
             float*       __restrict__ out,
             int P, int N)
{
    const int t  = blockIdx.x * blockDim.x + threadIdx.x;
    const int p0 = t * 8;
    if (p0 >= P) return;

    const float Lx = __ldg(box + 0);
    const float Ly = __ldg(box + 4);
    const float Lz = __ldg(box + 8);
    const float hx = 0.5f * Lx, hy = 0.5f * Ly, hz = 0.5f * Lz;
    const float CUTOFF = 0.5f;
    const size_t Ps = (size_t)P;

    if (p0 + 7 < P) {
        // ---- recover (i, j) for the 8 consecutive pairs ----
        int i = row_of(p0, N);
        int j = i + 1 + (p0 - row_start(i, N));

        int is[8], js[8];
        float fi[8], fj[8];
        #pragma unroll
        for (int k = 0; k < 8; k++) {
            is[k] = i; js[k] = j;
            fi[k] = (float)i; fj[k] = (float)j;
            ++j;
            if (j >= N) { ++i; j = i + 1; }
        }

        // Index regions early: DRAM busy while position gathers are in flight.
        st8(out + 0 * Ps + p0, fi[0],fi[1],fi[2],fi[3],fi[4],fi[5],fi[6],fi[7]);
        st8(out + 1 * Ps + p0, fj[0],fj[1],fj[2],fj[3],fj[4],fj[5],fj[6],fj[7]);
        st8(out + 2 * Ps + p0, fj[0],fj[1],fj[2],fj[3],fj[4],fj[5],fj[6],fj[7]);
        st8(out + 3 * Ps + p0, fi[0],fi[1],fi[2],fi[3],fi[4],fi[5],fi[6],fi[7]);

        // pi gather; dedupe when all 8 pairs share row i (the common case)
        float ax[8], ay[8], az[8];
        if (is[0] == is[7]) {
            const float* pi = pos + 3 * (size_t)is[0];
            float x = __ldg(pi + 0), y = __ldg(pi + 1), z = __ldg(pi + 2);
            #pragma unroll
            for (int k = 0; k < 8; k++) { ax[k] = x; ay[k] = y; az[k] = z; }
        } else {
            #pragma unroll
            for (int k = 0; k < 8; k++) {
                const float* pi = pos + 3 * (size_t)is[k];
                ax[k] = __ldg(pi + 0); ay[k] = __ldg(pi + 1); az[k] = __ldg(pi + 2);
            }
        }

        float rx[8], ry[8], rz[8], dd[8], mk[8];
        #pragma unroll
        for (int k = 0; k < 8; k++) {
            const float* pj = pos + 3 * (size_t)js[k];
            float x = ax[k] - __ldg(pj + 0);
            float y = ay[k] - __ldg(pj + 1);
            float z = az[k] - __ldg(pj + 2);
            x = wrap_pbc(x, Lx, hx);
            y = wrap_pbc(y, Ly, hy);
            z = wrap_pbc(z, Lz, hz);
            float d = sqrtf(x * x + y * y + z * z);
            bool m = (d <= CUTOFF);
            rx[k] = m ? x : 0.0f;
            ry[k] = m ? y : 0.0f;
            rz[k] = m ? z : 0.0f;
            dd[k] = m ? d : 0.0f;
            mk[k] = m ? 1.0f : 0.0f;
        }

        st8(out + 4 * Ps + p0, dd[0],dd[1],dd[2],dd[3],dd[4],dd[5],dd[6],dd[7]);
        st8(out + 5 * Ps + p0, dd[0],dd[1],dd[2],dd[3],dd[4],dd[5],dd[6],dd[7]);

        float* rp = out + 6 * Ps + 3 * (size_t)p0;
        st8(rp +  0, rx[0],ry[0],rz[0], rx[1],ry[1],rz[1], rx[2],ry[2]);
        st8(rp +  8, rz[2], rx[3],ry[3],rz[3], rx[4],ry[4],rz[4], rx[5]);
        st8(rp + 16, ry[5],rz[5], rx[6],ry[6],rz[6], rx[7],ry[7],rz[7]);

        float* rn = out + 9 * Ps + 3 * (size_t)p0;
        st8(rn +  0, -rx[0],-ry[0],-rz[0], -rx[1],-ry[1],-rz[1], -rx[2],-ry[2]);
        st8(rn +  8, -rz[2], -rx[3],-ry[3],-rz[3], -rx[4],-ry[4],-rz[4], -rx[5]);
        st8(rn + 16, -ry[5],-rz[5], -rx[6],-ry[6],-rz[6], -rx[7],-ry[7],-rz[7]);

        st8(out + 12 * Ps + p0, mk[0],mk[1],mk[2],mk[3],mk[4],mk[5],mk[6],mk[7]);
        st8(out + 13 * Ps + p0, mk[0],mk[1],mk[2],mk[3],mk[4],mk[5],mk[6],mk[7]);
    } else {
        // ---- scalar tail ----
        for (int p = p0; p < P; p++) {
            int i = row_of(p, N);
            int j = i + 1 + (p - row_start(i, N));
            const float* pi = pos + 3 * (size_t)i;
            const float* pj = pos + 3 * (size_t)j;
            float x = __ldg(pi + 0) - __ldg(pj + 0);
            float y = __ldg(pi + 1) - __ldg(pj + 1);
            float z = __ldg(pi + 2) - __ldg(pj + 2);
            x = wrap_pbc(x, Lx, hx);
            y = wrap_pbc(y, Ly, hy);
            z = wrap_pbc(z, Lz, hz);
            float d = sqrtf(x * x + y * y + z * z);
            bool m = (d <= CUTOFF);
            float mx = m ? x : 0.0f, my = m ? y : 0.0f, mz = m ? z : 0.0f;
            float md = m ? d : 0.0f, mv = m ? 1.0f : 0.0f;

            out[ 0 * Ps + p] = (float)i;
            out[ 1 * Ps + p] = (float)j;
            out[ 2 * Ps + p] = (float)j;
            out[ 3 * Ps + p] = (float)i;
            out[ 4 * Ps + p] = md;
            out[ 5 * Ps + p] = md;
            out[ 6 * Ps + 3 * (size_t)p + 0] =  mx;
            out[ 6 * Ps + 3 * (size_t)p + 1] =  my;
            out[ 6 * Ps + 3 * (size_t)p + 2] =  mz;
            out[ 9 * Ps + 3 * (size_t)p + 0] = -mx;
            out[ 9 * Ps + 3 * (size_t)p + 1] = -my;
            out[ 9 * Ps + 3 * (size_t)p + 2] = -mz;
            out[12 * Ps + p] = mv;
            out[13 * Ps + p] = mv;
        }
    }
}

extern "C" void kernel_launch(void* const* d_in, const int* in_sizes, int n_in,
                              void* d_out, int out_size)
{
    const float* pos = (const float*)d_in[0];   // [N,3] float32
    const float* box = (const float*)d_in[1];   // [3,3] float32
    // d_in[2]/d_in[3] (i_pairs/j_pairs) reconstructed analytically — not read.
    float* out = (float*)d_out;

    const int P = in_sizes[2];
    const int N = in_sizes[0] / 3;
    const int nthreads = (P + 7) / 8;
    const int block = 256;
    const int grid = (nthreads + block - 1) / block;
    nlist_kernel<<<grid, block>>>(pos, box, out, P, N);
}